// round 15
// baseline (speedup 1.0000x reference)
#include <cuda_runtime.h>
#include <cstdint>
#include <math.h>

// ---------------- problem constants ----------------
#define BB   4
#define PP   2048
#define DD   1024
#define HH   16
#define KVH  8
#define HDIM 64
#define FFN  4096
#define NE   16
#define FE   256
#define NTOK (BB*PP)          // 8192

// ---------------- scratch (no allocs allowed) ----------------
__device__ float g_h   [(size_t)NTOK*DD];
__device__ float g_q   [(size_t)NTOK*HH*HDIM];
__device__ float g_k   [(size_t)NTOK*KVH*HDIM];
__device__ float g_v   [(size_t)NTOK*KVH*HDIM];
__device__ float g_att [(size_t)NTOK*DD];
__device__ float g_x2  [(size_t)NTOK*DD];
__device__ float g_h2  [(size_t)NTOK*DD];
__device__ float g_gate[(size_t)NTOK*FFN];
__device__ float g_up  [(size_t)NTOK*FFN];
__device__ float g_eg  [(size_t)NTOK*NE*FE];
__device__ float g_eu  [(size_t)NTOK*NE*FE];
__device__ float g_tmp [(size_t)NTOK*DD];
// pre-rounded (tf32-RNA) weights
__device__ float g_wq [(size_t)DD*DD];
__device__ float g_wk [(size_t)DD*KVH*HDIM];
__device__ float g_wv [(size_t)DD*KVH*HDIM];
__device__ float g_wo [(size_t)DD*DD];
__device__ float g_wg [(size_t)DD*FFN];
__device__ float g_wu [(size_t)DD*FFN];
__device__ float g_wd [(size_t)FFN*DD];
__device__ float g_weg[(size_t)NE*DD*FE];
__device__ float g_weu[(size_t)NE*DD*FE];
__device__ float g_wed[(size_t)NE*FE*DD];
// rope cos/sin table [p][i][{cos,sin}]
__device__ float g_rope[(size_t)PP*32*2];

// =================== common helpers ===================
// tf32 HMMA reads only the upper 19 bits of each fp32-bit operand register:
// raw fp32 bits == RZ truncation. We pre-round all operands with RNA at the
// producers, making the in-loop truncation an identity (full-RNA numerics,
// zero hot-loop cvt instructions).
__device__ __forceinline__ float rna_tf32(float f) {
    uint32_t u;
    asm("cvt.rna.tf32.f32 %0, %1;" : "=r"(u) : "f"(f));
    return __uint_as_float(u);
}
__device__ __forceinline__ uint32_t smem_u32(const void* p) {
    uint32_t a;
    asm("{ .reg .u64 t; cvta.to.shared.u64 t, %1; cvt.u32.u64 %0, t; }" : "=r"(a) : "l"(p));
    return a;
}
__device__ __forceinline__ void mma_tf32(float* d, const uint32_t* a, const uint32_t* b) {
    asm volatile(
        "mma.sync.aligned.m16n8k8.row.col.f32.tf32.tf32.f32 "
        "{%0,%1,%2,%3}, {%4,%5,%6,%7}, {%8,%9}, {%0,%1,%2,%3};"
        : "+f"(d[0]), "+f"(d[1]), "+f"(d[2]), "+f"(d[3])
        : "r"(a[0]), "r"(a[1]), "r"(a[2]), "r"(a[3]), "r"(b[0]), "r"(b[1]));
}
#define CP16(dst, src) \
    asm volatile("cp.async.cg.shared.global [%0], [%1], 16;" :: "r"(dst), "l"(src))
#define CP_COMMIT() asm volatile("cp.async.commit_group;" ::: "memory")
#define CP_WAIT1()  asm volatile("cp.async.wait_group 1;" ::: "memory")

__device__ __forceinline__ float silu_f(float x) {
    return x / (1.0f + __expf(-x));
}
#define F2U __float_as_uint
#define U2F __uint_as_float

// ---------------- weight pre-round (tf32 RNA), float4 vectorized ----------------
__global__ void round_tf32_kernel(const float* __restrict__ in, float* __restrict__ out, long n4)
{
    long i = (long)blockIdx.x * blockDim.x + threadIdx.x;
    if (i < n4) {
        float4 v = ((const float4*)in)[i];
        v.x = rna_tf32(v.x); v.y = rna_tf32(v.y);
        v.z = rna_tf32(v.z); v.w = rna_tf32(v.w);
        ((float4*)out)[i] = v;
    }
}

// ---------------- rope table ----------------
__global__ void rope_table_kernel(float* __restrict__ tab)
{
    int idx = blockIdx.x * blockDim.x + threadIdx.x;   // PP*32
    int p = idx >> 5, i = idx & 31;
    float inv = powf(10000.0f, -(float)i * (1.0f/32.0f));
    float ang = (float)p * inv;
    tab[idx*2]   = cosf(ang);
    tab[idx*2+1] = sinf(ang);
}

// =================== tf32 mma.sync GEMM, cp.async 3-stage ===================
#define ASTR 36
#define BSTR 136
#define ASZ  (128*ASTR)
#define BSZ  (32*BSTR)
#define STG  (ASZ+BSZ)
#define MG_SMEM (3*STG*4)

template<int EPI>
__global__ __launch_bounds__(256, 2)
void mgemm_kernel(const float* __restrict__ A, const float* __restrict__ B,
                  float* __restrict__ C, int M, int N, int K, int ldc,
                  const float* __restrict__ bias, const float* __restrict__ res,
                  const float* __restrict__ mask, long sB, long sC)
{
    extern __shared__ __align__(16) float sm[];
    const uint32_t sb = smem_u32(sm);
    const int z = blockIdx.z;
    B += (long)z * sB;
    C += (long)z * sC;
    if (EPI >= 2) res += (long)z * sC;

    const int bm = blockIdx.y * 128, bn = blockIdx.x * 128;
    const int tid  = threadIdx.x;
    const int wid  = tid >> 5, lane = tid & 31;
    const int wm   = (wid & 1) * 64;
    const int wn   = (wid >> 1) * 32;
    const int gid  = lane >> 2;
    const int tig  = lane & 3;

    const int ar = tid >> 3, akc = tid & 7;
    const int br = tid >> 5, bc4 = tid & 31;
    auto load_stage = [&](int t) {
        const int k0 = t * 32;
        const uint32_t base = sb + (uint32_t)((t % 3) * STG) * 4u;
        #pragma unroll
        for (int j = 0; j < 4; j++) {
            int row = ar + j*32;
            CP16(base + (uint32_t)(row*ASTR + akc*4)*4u,
                 A + (size_t)(bm + row) * K + k0 + akc*4);
        }
        #pragma unroll
        for (int j = 0; j < 4; j++) {
            int row = br + j*8;
            CP16(base + (uint32_t)(ASZ + row*BSTR + bc4*4)*4u,
                 B + (size_t)(k0 + row) * N + bn + bc4*4);
        }
    };

    float acc[4][4][4];
    #pragma unroll
    for (int mt = 0; mt < 4; mt++)
        #pragma unroll
        for (int nt = 0; nt < 4; nt++)
            acc[mt][nt][0]=acc[mt][nt][1]=acc[mt][nt][2]=acc[mt][nt][3]=0.0f;

    const int KT = K / 32;
    load_stage(0); CP_COMMIT();
    load_stage(1); CP_COMMIT();

    for (int t = 0; t < KT; t++) {
        CP_WAIT1();
        __syncthreads();
        if (t + 2 < KT) load_stage(t + 2);
        CP_COMMIT();

        const float* aS = sm + (t % 3) * STG;
        const float* bS = aS + ASZ;
        #pragma unroll
        for (int kk = 0; kk < 4; kk++) {
            const int kb = kk * 8;
            uint32_t af[4][4], bf[4][2];
            #pragma unroll
            for (int mt = 0; mt < 4; mt++) {
                const int m0 = wm + mt*16;
                af[mt][0] = F2U(aS[(m0+gid  )*ASTR + kb+tig  ]);
                af[mt][1] = F2U(aS[(m0+gid+8)*ASTR + kb+tig  ]);
                af[mt][2] = F2U(aS[(m0+gid  )*ASTR + kb+tig+4]);
                af[mt][3] = F2U(aS[(m0+gid+8)*ASTR + kb+tig+4]);
            }
            #pragma unroll
            for (int nt = 0; nt < 4; nt++) {
                const int n0 = wn + nt*8;
                bf[nt][0] = F2U(bS[(kb+tig  )*BSTR + n0+gid]);
                bf[nt][1] = F2U(bS[(kb+tig+4)*BSTR + n0+gid]);
            }
            #pragma unroll
            for (int mt = 0; mt < 4; mt++)
                #pragma unroll
                for (int nt = 0; nt < 4; nt++)
                    mma_tf32(acc[mt][nt], af[mt], bf[nt]);
        }
        __syncthreads();
    }

    #pragma unroll
    for (int mt = 0; mt < 4; mt++) {
        #pragma unroll
        for (int half = 0; half < 2; half++) {
            const int r = bm + wm + mt*16 + gid + half*8;
            float mrow = 0.0f;
            if (EPI == 4) mrow = mask[(size_t)r * NE + z];
            #pragma unroll
            for (int nt = 0; nt < 4; nt++) {
                const int c = bn + wn + nt*8 + tig*2;
                float2 o;
                o.x = acc[mt][nt][half*2 + 0];
                o.y = acc[mt][nt][half*2 + 1];
                if (EPI == 1) {   // q/k/v: rounded (rope re-rounds q,k; v stays exact tf32)
                    o.x = rna_tf32(o.x + bias[c]);
                    o.y = rna_tf32(o.y + bias[c+1]);
                }
                if (EPI == 2) {   // residual carriers: full fp32
                    float2 rv = *(const float2*)(res + (size_t)r * ldc + c);
                    o.x += rv.x; o.y += rv.y;
                }
                if (EPI == 3) {   // gate: feeds w_down GEMM -> round
                    float2 rv = *(const float2*)(res + (size_t)r * ldc + c);
                    o.x = rna_tf32(silu_f(o.x) * rv.x);
                    o.y = rna_tf32(silu_f(o.y) * rv.y);
                }
                if (EPI == 4) {   // eg: feeds we_down GEMM -> round
                    float2 rv = *(const float2*)(res + (size_t)r * ldc + c);
                    o.x = rna_tf32(silu_f(o.x) * rv.x * mrow);
                    o.y = rna_tf32(silu_f(o.y) * rv.y * mrow);
                }
                *(float2*)(C + (size_t)r * ldc + c) = o;
            }
        }
    }
}

// ---------------- RMSNorm (output feeds GEMMs -> round to tf32 RNA) ----------------
__global__ void rmsnorm_kernel(const float* __restrict__ x, const float* __restrict__ w,
                               float* __restrict__ out)
{
    int row = blockIdx.x;
    int tid = threadIdx.x;
    const float4 v = ((const float4*)(x + (size_t)row*DD))[tid];
    float ss = v.x*v.x + v.y*v.y + v.z*v.z + v.w*v.w;
    #pragma unroll
    for (int o = 16; o; o >>= 1) ss += __shfl_xor_sync(0xffffffffu, ss, o);
    __shared__ float red[8];
    if ((tid & 31) == 0) red[tid >> 5] = ss;
    __syncthreads();
    float total = red[0]+red[1]+red[2]+red[3]+red[4]+red[5]+red[6]+red[7];
    float sc = rsqrtf(total * (1.0f/DD) + 1e-6f);
    const float4 wv = ((const float4*)w)[tid];
    float4 o4;
    o4.x = rna_tf32(v.x*sc*wv.x); o4.y = rna_tf32(v.y*sc*wv.y);
    o4.z = rna_tf32(v.z*sc*wv.z); o4.w = rna_tf32(v.w*sc*wv.w);
    ((float4*)(out + (size_t)row*DD))[tid] = o4;
}

// ---------------- RoPE (table-based; output rounded) ----------------
__global__ void rope_kernel(float* __restrict__ buf, const float* __restrict__ tab,
                            int nheads, long total)
{
    long idx = (long)blockIdx.x * blockDim.x + threadIdx.x;
    if (idx >= total) return;
    int  i    = (int)(idx & 31);
    int  head = (int)((idx >> 5) % nheads);
    long t    = idx / (32L * nheads);
    int  p    = (int)(t % PP);
    float2 cs = *(const float2*)(tab + ((size_t)p*32 + i)*2);
    float* v = buf + t * ((size_t)nheads * HDIM) + (size_t)head * HDIM + i;
    float a = v[0], b = v[32];
    v[0]  = rna_tf32(a*cs.x - b*cs.y);
    v[32] = rna_tf32(b*cs.x + a*cs.y);
}

// ---------------- tf32 tensor-core causal flash attention ----------------
#define FSTR 68
#define VSTR 72
#define FL_SMEM ((3*64*FSTR + 64*VSTR)*4)   // 70656 B

__global__ __launch_bounds__(128, 3)
void flash_tc_kernel(const float* __restrict__ q, const float* __restrict__ k,
                     const float* __restrict__ v, float* __restrict__ out)
{
    extern __shared__ float sm[];
    float* qs = sm;                 // [64][FSTR]
    float* ks = sm + 64*FSTR;       // [64][FSTR]
    float* ps = sm + 2*64*FSTR;     // [64][FSTR]
    float* vs = sm + 3*64*FSTR;     // [64][VSTR]

    const int b = blockIdx.z, h = blockIdx.y, qt = blockIdx.x;
    const int q0 = qt * 64;
    const float* qb = q + (size_t)b*PP*(HH*HDIM)  + (size_t)h*HDIM;
    const float* kb = k + (size_t)b*PP*(KVH*HDIM) + (size_t)(h>>1)*HDIM;
    const float* vb = v + (size_t)b*PP*(KVH*HDIM) + (size_t)(h>>1)*HDIM;

    const int tid = threadIdx.x;
    const int wid = tid >> 5, lane = tid & 31;
    const int gid = lane >> 2, tig = lane & 3;
    const int m0  = wid * 16;

    // load Q tile (x0.125 keeps tf32-roundedness: power-of-two scale)
    #pragma unroll
    for (int i = 0; i < 8; i++) {
        int idx = tid + i*128;
        int row = idx >> 4, c4 = (idx & 15) * 4;
        float4 a = *(const float4*)(qb + (size_t)(q0+row)*(HH*HDIM) + c4);
        a.x *= 0.125f; a.y *= 0.125f; a.z *= 0.125f; a.w *= 0.125f;
        *(float4*)(qs + row*FSTR + c4) = a;
    }

    float m_i[2] = {-1e30f, -1e30f};
    float l_i[2] = {0.0f, 0.0f};
    float o[8][4];
    #pragma unroll
    for (int j = 0; j < 8; j++) o[j][0]=o[j][1]=o[j][2]=o[j][3]=0.0f;

    for (int t = 0; t <= qt; t++) {
        const int k0 = t * 64;
        __syncthreads();
        #pragma unroll
        for (int i = 0; i < 8; i++) {
            int idx = tid + i*128;
            int row = idx >> 4, c4 = (idx & 15) * 4;
            *(float4*)(ks + row*FSTR + c4) =
                *(const float4*)(kb + (size_t)(k0+row)*(KVH*HDIM) + c4);
            *(float4*)(vs + row*VSTR + c4) =
                *(const float4*)(vb + (size_t)(k0+row)*(KVH*HDIM) + c4);
        }
        __syncthreads();

        // S = Q @ K^T   (m16 x n64 per warp)
        float sacc[8][4];
        #pragma unroll
        for (int j = 0; j < 8; j++) sacc[j][0]=sacc[j][1]=sacc[j][2]=sacc[j][3]=0.0f;
        #pragma unroll
        for (int kc = 0; kc < 8; kc++) {
            const int kb8 = kc * 8;
            uint32_t av[4];
            av[0] = F2U(qs[(m0+gid  )*FSTR + kb8+tig  ]);
            av[1] = F2U(qs[(m0+gid+8)*FSTR + kb8+tig  ]);
            av[2] = F2U(qs[(m0+gid  )*FSTR + kb8+tig+4]);
            av[3] = F2U(qs[(m0+gid+8)*FSTR + kb8+tig+4]);
            #pragma unroll
            for (int j = 0; j < 8; j++) {
                uint32_t bv[2];
                bv[0] = F2U(ks[(j*8+gid)*FSTR + kb8+tig  ]);
                bv[1] = F2U(ks[(j*8+gid)*FSTR + kb8+tig+4]);
                mma_tf32(sacc[j], av, bv);
            }
        }

        if (t == qt) {
            #pragma unroll
            for (int j = 0; j < 8; j++)
                #pragma unroll
                for (int e = 0; e < 4; e++) {
                    int row = q0 + m0 + gid + ((e >> 1) << 3);
                    int col = k0 + j*8 + tig*2 + (e & 1);
                    if (col > row) sacc[j][e] = -1e30f;
                }
        }

        #pragma unroll
        for (int r = 0; r < 2; r++) {
            float rm = -1e30f;
            #pragma unroll
            for (int j = 0; j < 8; j++)
                rm = fmaxf(rm, fmaxf(sacc[j][r*2], sacc[j][r*2+1]));
            rm = fmaxf(rm, __shfl_xor_sync(0xffffffffu, rm, 1));
            rm = fmaxf(rm, __shfl_xor_sync(0xffffffffu, rm, 2));
            float nm = fmaxf(m_i[r], rm);
            float corr = __expf(m_i[r] - nm);
            m_i[r] = nm;
            float rs = 0.0f;
            #pragma unroll
            for (int j = 0; j < 8; j++) {
                float p0 = __expf(sacc[j][r*2  ] - nm);
                float p1 = __expf(sacc[j][r*2+1] - nm);
                sacc[j][r*2] = p0; sacc[j][r*2+1] = p1;
                rs += p0 + p1;
            }
            rs += __shfl_xor_sync(0xffffffffu, rs, 1);
            rs += __shfl_xor_sync(0xffffffffu, rs, 2);
            l_i[r] = l_i[r]*corr + rs;
            #pragma unroll
            for (int j = 0; j < 8; j++) { o[j][r*2] *= corr; o[j][r*2+1] *= corr; }
        }

        // store P (raw fp32 bits; RZ at PV read — P in [0,1], bias negligible)
        #pragma unroll
        for (int j = 0; j < 8; j++) {
            *(float2*)(ps + (m0+gid  )*FSTR + j*8 + tig*2) = make_float2(sacc[j][0], sacc[j][1]);
            *(float2*)(ps + (m0+gid+8)*FSTR + j*8 + tig*2) = make_float2(sacc[j][2], sacc[j][3]);
        }
        __syncwarp();

        // O += P @ V
        #pragma unroll
        for (int kc = 0; kc < 8; kc++) {
            const int kb8 = kc * 8;
            uint32_t av[4];
            av[0] = F2U(ps[(m0+gid  )*FSTR + kb8+tig  ]);
            av[1] = F2U(ps[(m0+gid+8)*FSTR + kb8+tig  ]);
            av[2] = F2U(ps[(m0+gid  )*FSTR + kb8+tig+4]);
            av[3] = F2U(ps[(m0+gid+8)*FSTR + kb8+tig+4]);
            #pragma unroll
            for (int j = 0; j < 8; j++) {
                uint32_t bv[2];
                bv[0] = F2U(vs[(kb8+tig  )*VSTR + j*8+gid]);
                bv[1] = F2U(vs[(kb8+tig+4)*VSTR + j*8+gid]);
                mma_tf32(o[j], av, bv);
            }
        }
    }

    const float inv0 = 1.0f / l_i[0];
    const float inv1 = 1.0f / l_i[1];
    float* ob = out + (size_t)b*PP*DD + (size_t)h*HDIM;
    #pragma unroll
    for (int j = 0; j < 8; j++) {
        int c = j*8 + tig*2;
        *(float2*)(ob + (size_t)(q0+m0+gid  )*DD + c) =
            make_float2(rna_tf32(o[j][0]*inv0), rna_tf32(o[j][1]*inv0));
        *(float2*)(ob + (size_t)(q0+m0+gid+8)*DD + c) =
            make_float2(rna_tf32(o[j][2]*inv1), rna_tf32(o[j][3]*inv1));
    }
}

// ---------------- launch ----------------
extern "C" void kernel_launch(void* const* d_in, const int* in_sizes, int n_in,
                              void* d_out, int out_size)
{
    const float* x        = (const float*)d_in[0];
    const float* emask    = (const float*)d_in[1];
    const float* ln1_w    = (const float*)d_in[2];
    const float* wq       = (const float*)d_in[3];
    const float* bq       = (const float*)d_in[4];
    const float* wk       = (const float*)d_in[5];
    const float* bk       = (const float*)d_in[6];
    const float* wv       = (const float*)d_in[7];
    const float* bv       = (const float*)d_in[8];
    const float* wo       = (const float*)d_in[9];
    const float* ln2_w    = (const float*)d_in[10];
    const float* w_gate   = (const float*)d_in[11];
    const float* w_up     = (const float*)d_in[12];
    const float* w_down   = (const float*)d_in[13];
    const float* we_gate  = (const float*)d_in[14];
    const float* we_up    = (const float*)d_in[15];
    const float* we_down  = (const float*)d_in[16];
    float* out = (float*)d_out;

    float *h,*q,*k,*v,*att,*x2,*h2,*gate,*up,*eg,*eu,*tmp;
    float *wqr,*wkr,*wvr,*wor,*wgr,*wur,*wdr,*wegr,*weur,*wedr,*ropet;
    cudaGetSymbolAddress((void**)&h,   g_h);
    cudaGetSymbolAddress((void**)&q,   g_q);
    cudaGetSymbolAddress((void**)&k,   g_k);
    cudaGetSymbolAddress((void**)&v,   g_v);
    cudaGetSymbolAddress((void**)&att, g_att);
    cudaGetSymbolAddress((void**)&x2,  g_x2);
    cudaGetSymbolAddress((void**)&h2,  g_h2);
    cudaGetSymbolAddress((void**)&gate,g_gate);
    cudaGetSymbolAddress((void**)&up,  g_up);
    cudaGetSymbolAddress((void**)&eg,  g_eg);
    cudaGetSymbolAddress((void**)&eu,  g_eu);
    cudaGetSymbolAddress((void**)&tmp, g_tmp);
    cudaGetSymbolAddress((void**)&wqr, g_wq);
    cudaGetSymbolAddress((void**)&wkr, g_wk);
    cudaGetSymbolAddress((void**)&wvr, g_wv);
    cudaGetSymbolAddress((void**)&wor, g_wo);
    cudaGetSymbolAddress((void**)&wgr, g_wg);
    cudaGetSymbolAddress((void**)&wur, g_wu);
    cudaGetSymbolAddress((void**)&wdr, g_wd);
    cudaGetSymbolAddress((void**)&wegr,g_weg);
    cudaGetSymbolAddress((void**)&weur,g_weu);
    cudaGetSymbolAddress((void**)&wedr,g_wed);
    cudaGetSymbolAddress((void**)&ropet,g_rope);

    cudaFuncSetAttribute(mgemm_kernel<0>, cudaFuncAttributeMaxDynamicSharedMemorySize, MG_SMEM);
    cudaFuncSetAttribute(mgemm_kernel<1>, cudaFuncAttributeMaxDynamicSharedMemorySize, MG_SMEM);
    cudaFuncSetAttribute(mgemm_kernel<2>, cudaFuncAttributeMaxDynamicSharedMemorySize, MG_SMEM);
    cudaFuncSetAttribute(mgemm_kernel<3>, cudaFuncAttributeMaxDynamicSharedMemorySize, MG_SMEM);
    cudaFuncSetAttribute(mgemm_kernel<4>, cudaFuncAttributeMaxDynamicSharedMemorySize, MG_SMEM);
    cudaFuncSetAttribute(flash_tc_kernel, cudaFuncAttributeMaxDynamicSharedMemorySize, FL_SMEM);

    // 0) pre-round weights to tf32-RNA; build rope table
    auto rw = [&](const float* src, float* dst, long n) {
        long n4 = n / 4;
        round_tf32_kernel<<<(unsigned)((n4 + 255) / 256), 256>>>(src, dst, n4);
    };
    rw(wq, wqr, (long)DD*DD);
    rw(wk, wkr, (long)DD*KVH*HDIM);
    rw(wv, wvr, (long)DD*KVH*HDIM);
    rw(wo, wor, (long)DD*DD);
    rw(w_gate, wgr, (long)DD*FFN);
    rw(w_up,   wur, (long)DD*FFN);
    rw(w_down, wdr, (long)FFN*DD);
    rw(we_gate, wegr, (long)NE*DD*FE);
    rw(we_up,   weur, (long)NE*DD*FE);
    rw(we_down, wedr, (long)NE*FE*DD);
    rope_table_kernel<<<PP*32/256, 256>>>(ropet);

    // 1) h = rmsnorm(x)   (tf32-rounded)
    rmsnorm_kernel<<<NTOK, 256>>>(x, ln1_w, h);

    // 2) QKV projections (+bias, rounded)
    mgemm_kernel<1><<<dim3(8,64,1), 256, MG_SMEM>>>(h, wqr, q, NTOK, 1024, 1024, 1024, bq, nullptr, nullptr, 0, 0);
    mgemm_kernel<1><<<dim3(4,64,1), 256, MG_SMEM>>>(h, wkr, k, NTOK,  512, 1024,  512, bk, nullptr, nullptr, 0, 0);
    mgemm_kernel<1><<<dim3(4,64,1), 256, MG_SMEM>>>(h, wvr, v, NTOK,  512, 1024,  512, bv, nullptr, nullptr, 0, 0);

    // 3) RoPE (table-based, rounded)
    {
        long tq = (long)NTOK * HH  * 32;
        rope_kernel<<<(unsigned)((tq + 255) / 256), 256>>>(q, ropet, HH, tq);
        long tk = (long)NTOK * KVH * 32;
        rope_kernel<<<(unsigned)((tk + 255) / 256), 256>>>(k, ropet, KVH, tk);
    }

    // 4) attention (tf32 tensor cores; output rounded)
    flash_tc_kernel<<<dim3(PP/64, HH, BB), 128, FL_SMEM>>>(q, k, v, att);

    // 5) x2 = x + att @ wo
    mgemm_kernel<2><<<dim3(8,64,1), 256, MG_SMEM>>>(att, wor, x2, NTOK, 1024, 1024, 1024, nullptr, x, nullptr, 0, 0);

    // 6) h2 = rmsnorm(x2)   (rounded)
    rmsnorm_kernel<<<NTOK, 256>>>(x2, ln2_w, h2);

    // 7) dense MLP: up first, then gate with fused silu*up (rounded), then down(+res)
    mgemm_kernel<0><<<dim3(32,64,1), 256, MG_SMEM>>>(h2, wur, up,   NTOK, 4096, 1024, 4096, nullptr, nullptr, nullptr, 0, 0);
    mgemm_kernel<3><<<dim3(32,64,1), 256, MG_SMEM>>>(h2, wgr, gate, NTOK, 4096, 1024, 4096, nullptr, up,      nullptr, 0, 0);
    mgemm_kernel<2><<<dim3(8,64,1),  256, MG_SMEM>>>(gate, wdr, tmp, NTOK, 1024, 4096, 1024, nullptr, x2,     nullptr, 0, 0);

    // 8) experts (z-batched): eu first, then eg with fused silu*eu*mask (rounded)
    mgemm_kernel<0><<<dim3(2,64,NE), 256, MG_SMEM>>>(h2, weur, eu, NTOK, 256, 1024, 4096,
                                                     nullptr, nullptr, nullptr, (long)1024*256, 256);
    mgemm_kernel<4><<<dim3(2,64,NE), 256, MG_SMEM>>>(h2, wegr, eg, NTOK, 256, 1024, 4096,
                                                     nullptr, eu, emask, (long)1024*256, 256);
    // 9) out = tmp + expert_acts @ we_down
    mgemm_kernel<2><<<dim3(8,64,1), 256, MG_SMEM>>>(eg, wedr, out, NTOK, 1024, 4096, 1024, nullptr, tmp, nullptr, 0, 0);
}

// round 16
// speedup vs baseline: 1.0042x; 1.0042x over previous
#include <cuda_runtime.h>
#include <cstdint>
#include <math.h>

// ---------------- problem constants ----------------
#define BB   4
#define PP   2048
#define DD   1024
#define HH   16
#define KVH  8
#define HDIM 64
#define FFN  4096
#define NE   16
#define FE   256
#define NTOK (BB*PP)          // 8192

// ---------------- scratch (no allocs allowed) ----------------
__device__ float g_h   [(size_t)NTOK*DD];
__device__ float g_q   [(size_t)NTOK*HH*HDIM];
__device__ float g_k   [(size_t)NTOK*KVH*HDIM];
__device__ float g_v   [(size_t)NTOK*KVH*HDIM];
__device__ float g_att [(size_t)NTOK*DD];
__device__ float g_x2  [(size_t)NTOK*DD];
__device__ float g_h2  [(size_t)NTOK*DD];
__device__ float g_gate[(size_t)NTOK*FFN];
__device__ float g_up  [(size_t)NTOK*FFN];
__device__ float g_eg  [(size_t)NTOK*NE*FE];
__device__ float g_eu  [(size_t)NTOK*NE*FE];
__device__ float g_tmp [(size_t)NTOK*DD];
// pre-rounded (tf32-RNA) weights
__device__ float g_wq [(size_t)DD*DD];
__device__ float g_wk [(size_t)DD*KVH*HDIM];
__device__ float g_wv [(size_t)DD*KVH*HDIM];
__device__ float g_wo [(size_t)DD*DD];
__device__ float g_wg [(size_t)DD*FFN];
__device__ float g_wu [(size_t)DD*FFN];
__device__ float g_wd [(size_t)FFN*DD];
__device__ float g_weg[(size_t)NE*DD*FE];
__device__ float g_weu[(size_t)NE*DD*FE];
__device__ float g_wed[(size_t)NE*FE*DD];
// rope cos/sin table [p][i][{cos,sin}]
__device__ float g_rope[(size_t)PP*32*2];

// =================== common helpers ===================
// tf32 HMMA reads only the upper 19 bits of each fp32-bit operand register:
// raw fp32 bits == RZ truncation. All operands are RNA-rounded at producers,
// making the in-loop truncation an identity (full-RNA numerics, zero hot-loop cvt).
__device__ __forceinline__ float rna_tf32(float f) {
    uint32_t u;
    asm("cvt.rna.tf32.f32 %0, %1;" : "=r"(u) : "f"(f));
    return __uint_as_float(u);
}
__device__ __forceinline__ uint32_t smem_u32(const void* p) {
    uint32_t a;
    asm("{ .reg .u64 t; cvta.to.shared.u64 t, %1; cvt.u32.u64 %0, t; }" : "=r"(a) : "l"(p));
    return a;
}
__device__ __forceinline__ void mma_tf32(float* d, const uint32_t* a, const uint32_t* b) {
    asm volatile(
        "mma.sync.aligned.m16n8k8.row.col.f32.tf32.tf32.f32 "
        "{%0,%1,%2,%3}, {%4,%5,%6,%7}, {%8,%9}, {%0,%1,%2,%3};"
        : "+f"(d[0]), "+f"(d[1]), "+f"(d[2]), "+f"(d[3])
        : "r"(a[0]), "r"(a[1]), "r"(a[2]), "r"(a[3]), "r"(b[0]), "r"(b[1]));
}
#define CP16(dst, src) \
    asm volatile("cp.async.cg.shared.global [%0], [%1], 16;" :: "r"(dst), "l"(src))
#define CP_COMMIT() asm volatile("cp.async.commit_group;" ::: "memory")
#define CP_WAIT1()  asm volatile("cp.async.wait_group 1;" ::: "memory")

__device__ __forceinline__ float silu_f(float x) {
    return x / (1.0f + __expf(-x));
}
#define F2U __float_as_uint
#define U2F __uint_as_float

// ---------------- weight pre-round (tf32 RNA) ----------------
__global__ void round_tf32_kernel(const float* __restrict__ in, float* __restrict__ out, long n4)
{
    long i = (long)blockIdx.x * blockDim.x + threadIdx.x;
    if (i < n4) {
        float4 v = ((const float4*)in)[i];
        v.x = rna_tf32(v.x); v.y = rna_tf32(v.y);
        v.z = rna_tf32(v.z); v.w = rna_tf32(v.w);
        ((float4*)out)[i] = v;
    }
}

// ---------------- rope table ----------------
__global__ void rope_table_kernel(float* __restrict__ tab)
{
    int idx = blockIdx.x * blockDim.x + threadIdx.x;   // PP*32
    int p = idx >> 5, i = idx & 31;
    float inv = powf(10000.0f, -(float)i * (1.0f/32.0f));
    float ang = (float)p * inv;
    tab[idx*2]   = cosf(ang);
    tab[idx*2+1] = sinf(ang);
}

// =================== tf32 mma.sync GEMM, cp.async 3-stage ===================
#define ASTR 36
#define BSTR 136
#define ASZ  (128*ASTR)
#define BSZ  (32*BSTR)
#define STG  (ASZ+BSZ)
#define MG_SMEM (3*STG*4)

template<int EPI>
__global__ __launch_bounds__(256, 2)
void mgemm_kernel(const float* __restrict__ A, const float* __restrict__ B,
                  float* __restrict__ C, int M, int N, int K, int ldc,
                  const float* __restrict__ bias, const float* __restrict__ res,
                  const float* __restrict__ mask, long sB, long sC)
{
    extern __shared__ __align__(16) float sm[];
    const uint32_t sb = smem_u32(sm);
    const int z = blockIdx.z;
    B += (long)z * sB;
    C += (long)z * sC;
    if (EPI >= 2) res += (long)z * sC;

    const int bm = blockIdx.y * 128, bn = blockIdx.x * 128;
    const int tid  = threadIdx.x;
    const int wid  = tid >> 5, lane = tid & 31;
    const int wm   = (wid & 1) * 64;
    const int wn   = (wid >> 1) * 32;
    const int gid  = lane >> 2;
    const int tig  = lane & 3;

    const int ar = tid >> 3, akc = tid & 7;
    const int br = tid >> 5, bc4 = tid & 31;
    auto load_stage = [&](int t) {
        const int k0 = t * 32;
        const uint32_t base = sb + (uint32_t)((t % 3) * STG) * 4u;
        #pragma unroll
        for (int j = 0; j < 4; j++) {
            int row = ar + j*32;
            CP16(base + (uint32_t)(row*ASTR + akc*4)*4u,
                 A + (size_t)(bm + row) * K + k0 + akc*4);
        }
        #pragma unroll
        for (int j = 0; j < 4; j++) {
            int row = br + j*8;
            CP16(base + (uint32_t)(ASZ + row*BSTR + bc4*4)*4u,
                 B + (size_t)(k0 + row) * N + bn + bc4*4);
        }
    };

    float acc[4][4][4];
    #pragma unroll
    for (int mt = 0; mt < 4; mt++)
        #pragma unroll
        for (int nt = 0; nt < 4; nt++)
            acc[mt][nt][0]=acc[mt][nt][1]=acc[mt][nt][2]=acc[mt][nt][3]=0.0f;

    const int KT = K / 32;
    load_stage(0); CP_COMMIT();
    load_stage(1); CP_COMMIT();

    for (int t = 0; t < KT; t++) {
        CP_WAIT1();
        __syncthreads();
        if (t + 2 < KT) load_stage(t + 2);
        CP_COMMIT();

        const float* aS = sm + (t % 3) * STG;
        const float* bS = aS + ASZ;
        #pragma unroll
        for (int kk = 0; kk < 4; kk++) {
            const int kb = kk * 8;
            uint32_t af[4][4], bf[4][2];
            #pragma unroll
            for (int mt = 0; mt < 4; mt++) {
                const int m0 = wm + mt*16;
                af[mt][0] = F2U(aS[(m0+gid  )*ASTR + kb+tig  ]);
                af[mt][1] = F2U(aS[(m0+gid+8)*ASTR + kb+tig  ]);
                af[mt][2] = F2U(aS[(m0+gid  )*ASTR + kb+tig+4]);
                af[mt][3] = F2U(aS[(m0+gid+8)*ASTR + kb+tig+4]);
            }
            #pragma unroll
            for (int nt = 0; nt < 4; nt++) {
                const int n0 = wn + nt*8;
                bf[nt][0] = F2U(bS[(kb+tig  )*BSTR + n0+gid]);
                bf[nt][1] = F2U(bS[(kb+tig+4)*BSTR + n0+gid]);
            }
            #pragma unroll
            for (int mt = 0; mt < 4; mt++)
                #pragma unroll
                for (int nt = 0; nt < 4; nt++)
                    mma_tf32(acc[mt][nt], af[mt], bf[nt]);
        }
        __syncthreads();
    }

    #pragma unroll
    for (int mt = 0; mt < 4; mt++) {
        #pragma unroll
        for (int half = 0; half < 2; half++) {
            const int r = bm + wm + mt*16 + gid + half*8;
            float mrow = 0.0f;
            if (EPI == 4) mrow = mask[(size_t)r * NE + z];
            #pragma unroll
            for (int nt = 0; nt < 4; nt++) {
                const int c = bn + wn + nt*8 + tig*2;
                float2 o;
                o.x = acc[mt][nt][half*2 + 0];
                o.y = acc[mt][nt][half*2 + 1];
                if (EPI == 1) {   // q/k/v outputs feed attention: round
                    o.x = rna_tf32(o.x + bias[c]);
                    o.y = rna_tf32(o.y + bias[c+1]);
                }
                if (EPI == 2) {   // residual carriers: full fp32
                    float2 rv = *(const float2*)(res + (size_t)r * ldc + c);
                    o.x += rv.x; o.y += rv.y;
                }
                if (EPI == 3) {   // gate feeds w_down: round
                    float2 rv = *(const float2*)(res + (size_t)r * ldc + c);
                    o.x = rna_tf32(silu_f(o.x) * rv.x);
                    o.y = rna_tf32(silu_f(o.y) * rv.y);
                }
                if (EPI == 4) {   // eg feeds we_down: round
                    float2 rv = *(const float2*)(res + (size_t)r * ldc + c);
                    o.x = rna_tf32(silu_f(o.x) * rv.x * mrow);
                    o.y = rna_tf32(silu_f(o.y) * rv.y * mrow);
                }
                *(float2*)(C + (size_t)r * ldc + c) = o;
            }
        }
    }
}

// ---------------- RMSNorm (output rounded to tf32 RNA) ----------------
__global__ void rmsnorm_kernel(const float* __restrict__ x, const float* __restrict__ w,
                               float* __restrict__ out)
{
    int row = blockIdx.x;
    int tid = threadIdx.x;
    const float4 v = ((const float4*)(x + (size_t)row*DD))[tid];
    float ss = v.x*v.x + v.y*v.y + v.z*v.z + v.w*v.w;
    #pragma unroll
    for (int o = 16; o; o >>= 1) ss += __shfl_xor_sync(0xffffffffu, ss, o);
    __shared__ float red[8];
    if ((tid & 31) == 0) red[tid >> 5] = ss;
    __syncthreads();
    float total = red[0]+red[1]+red[2]+red[3]+red[4]+red[5]+red[6]+red[7];
    float sc = rsqrtf(total * (1.0f/DD) + 1e-6f);
    const float4 wv = ((const float4*)w)[tid];
    float4 o4;
    o4.x = rna_tf32(v.x*sc*wv.x); o4.y = rna_tf32(v.y*sc*wv.y);
    o4.z = rna_tf32(v.z*sc*wv.z); o4.w = rna_tf32(v.w*sc*wv.w);
    ((float4*)(out + (size_t)row*DD))[tid] = o4;
}

// ---------------- RoPE (table-based; output rounded) ----------------
__global__ void rope_kernel(float* __restrict__ buf, const float* __restrict__ tab,
                            int nheads, long total)
{
    long idx = (long)blockIdx.x * blockDim.x + threadIdx.x;
    if (idx >= total) return;
    int  i    = (int)(idx & 31);
    int  head = (int)((idx >> 5) % nheads);
    long t    = idx / (32L * nheads);
    int  p    = (int)(t % PP);
    float2 cs = *(const float2*)(tab + ((size_t)p*32 + i)*2);
    float* v = buf + t * ((size_t)nheads * HDIM) + (size_t)head * HDIM + i;
    float a = v[0], b = v[32];
    v[0]  = rna_tf32(a*cs.x - b*cs.y);
    v[32] = rna_tf32(b*cs.x + a*cs.y);
}

// ---------------- tf32 tensor-core causal flash attention v2 ----------------
// 128 q-rows/CTA, 8 warps (each m16n64), cp.async K/V with split-phase prefetch,
// warp-level causal skip, heavy-CTAs-first schedule.
#define QROWS 128
#define FSTR 68
#define VSTR 72
#define FL_SMEM ((QROWS*FSTR + 64*FSTR + QROWS*FSTR + 64*VSTR)*4)  // 105472 B

__global__ __launch_bounds__(256, 2)
void flash_tc_kernel(const float* __restrict__ q, const float* __restrict__ k,
                     const float* __restrict__ v, float* __restrict__ out)
{
    extern __shared__ float sm[];
    float* qs = sm;                              // [128][FSTR]
    float* ks = sm + QROWS*FSTR;                 // [64][FSTR]
    float* ps = sm + QROWS*FSTR + 64*FSTR;       // [128][FSTR]
    float* vs = ps + QROWS*FSTR;                 // [64][VSTR]
    const uint32_t sb  = smem_u32(sm);
    const uint32_t KSB = (uint32_t)(QROWS*FSTR)*4u;
    const uint32_t VSB = (uint32_t)(QROWS*FSTR + 64*FSTR + QROWS*FSTR)*4u;

    const int b = blockIdx.z, h = blockIdx.y;
    const int qtile = (int)(gridDim.x - 1 - blockIdx.x);   // heavy first
    const int q0 = qtile * QROWS;
    const int ktmax = 2*qtile + 2;

    const float* qb = q + (size_t)b*PP*(HH*HDIM)  + (size_t)h*HDIM;
    const float* kb = k + (size_t)b*PP*(KVH*HDIM) + (size_t)(h>>1)*HDIM;
    const float* vb = v + (size_t)b*PP*(KVH*HDIM) + (size_t)(h>>1)*HDIM;

    const int tid = threadIdx.x;
    const int wid = tid >> 5, lane = tid & 31;
    const int gid = lane >> 2, tig = lane & 3;
    const int m0  = wid * 16;

    // Q tile: LDG + prescale (power-of-two keeps tf32-roundedness) + STS
    #pragma unroll
    for (int i = 0; i < 8; i++) {
        int idx = tid + i*256;
        int row = idx >> 4, c4 = (idx & 15) * 4;
        float4 a = *(const float4*)(qb + (size_t)(q0+row)*(HH*HDIM) + c4);
        a.x *= 0.125f; a.y *= 0.125f; a.z *= 0.125f; a.w *= 0.125f;
        *(float4*)(qs + row*FSTR + c4) = a;
    }

    auto load_k = [&](int kt) {
        const int k0 = kt * 64;
        #pragma unroll
        for (int j = 0; j < 4; j++) {
            int c = tid + j*256;
            int row = c >> 4, c4 = (c & 15) * 4;
            CP16(sb + KSB + (uint32_t)(row*FSTR + c4)*4u,
                 kb + (size_t)(k0+row)*(KVH*HDIM) + c4);
        }
    };
    auto load_v = [&](int kt) {
        const int k0 = kt * 64;
        #pragma unroll
        for (int j = 0; j < 4; j++) {
            int c = tid + j*256;
            int row = c >> 4, c4 = (c & 15) * 4;
            CP16(sb + VSB + (uint32_t)(row*VSTR + c4)*4u,
                 vb + (size_t)(k0+row)*(KVH*HDIM) + c4);
        }
    };

    load_k(0); CP_COMMIT();
    load_v(0); CP_COMMIT();

    float m_i[2] = {-1e30f, -1e30f};
    float l_i[2] = {0.0f, 0.0f};
    float o[8][4];
    #pragma unroll
    for (int j = 0; j < 8; j++) o[j][0]=o[j][1]=o[j][2]=o[j][3]=0.0f;

    for (int kt = 0; kt < ktmax; kt++) {
        const int k0 = kt * 64;
        const bool active = (k0 <= q0 + m0 + 15);   // warp-level causal skip

        CP_WAIT1();              // K(kt) resident (V(kt) may still fly)
        __syncthreads();

        float sacc[8][4];
        if (active) {
            #pragma unroll
            for (int j = 0; j < 8; j++) sacc[j][0]=sacc[j][1]=sacc[j][2]=sacc[j][3]=0.0f;
            #pragma unroll
            for (int kc = 0; kc < 8; kc++) {
                const int kb8 = kc * 8;
                uint32_t av[4];
                av[0] = F2U(qs[(m0+gid  )*FSTR + kb8+tig  ]);
                av[1] = F2U(qs[(m0+gid+8)*FSTR + kb8+tig  ]);
                av[2] = F2U(qs[(m0+gid  )*FSTR + kb8+tig+4]);
                av[3] = F2U(qs[(m0+gid+8)*FSTR + kb8+tig+4]);
                #pragma unroll
                for (int j = 0; j < 8; j++) {
                    uint32_t bv[2];
                    bv[0] = F2U(ks[(j*8+gid)*FSTR + kb8+tig  ]);
                    bv[1] = F2U(ks[(j*8+gid)*FSTR + kb8+tig+4]);
                    mma_tf32(sacc[j], av, bv);
                }
            }
        }
        __syncthreads();         // ks consumed
        if (kt + 1 < ktmax) load_k(kt + 1);
        CP_COMMIT();             // K(kt+1) overlaps softmax+PV

        CP_WAIT1();              // V(kt) resident (K(kt+1) may still fly)
        __syncthreads();

        if (active) {
            if (k0 + 63 > q0 + m0) {   // partial causal mask
                #pragma unroll
                for (int j = 0; j < 8; j++)
                    #pragma unroll
                    for (int e = 0; e < 4; e++) {
                        int row = q0 + m0 + gid + ((e >> 1) << 3);
                        int col = k0 + j*8 + tig*2 + (e & 1);
                        if (col > row) sacc[j][e] = -1e30f;
                    }
            }

            #pragma unroll
            for (int r = 0; r < 2; r++) {
                float rm = -1e30f;
                #pragma unroll
                for (int j = 0; j < 8; j++)
                    rm = fmaxf(rm, fmaxf(sacc[j][r*2], sacc[j][r*2+1]));
                rm = fmaxf(rm, __shfl_xor_sync(0xffffffffu, rm, 1));
                rm = fmaxf(rm, __shfl_xor_sync(0xffffffffu, rm, 2));
                float nm = fmaxf(m_i[r], rm);
                float corr = __expf(m_i[r] - nm);
                m_i[r] = nm;
                float rs = 0.0f;
                #pragma unroll
                for (int j = 0; j < 8; j++) {
                    float p0 = __expf(sacc[j][r*2  ] - nm);
                    float p1 = __expf(sacc[j][r*2+1] - nm);
                    sacc[j][r*2] = p0; sacc[j][r*2+1] = p1;
                    rs += p0 + p1;
                }
                rs += __shfl_xor_sync(0xffffffffu, rs, 1);
                rs += __shfl_xor_sync(0xffffffffu, rs, 2);
                l_i[r] = l_i[r]*corr + rs;
                #pragma unroll
                for (int j = 0; j < 8; j++) { o[j][r*2] *= corr; o[j][r*2+1] *= corr; }
            }

            // store P (raw fp32 bits; RZ at PV read — P in [0,1], bias negligible)
            #pragma unroll
            for (int j = 0; j < 8; j++) {
                *(float2*)(ps + (m0+gid  )*FSTR + j*8 + tig*2) = make_float2(sacc[j][0], sacc[j][1]);
                *(float2*)(ps + (m0+gid+8)*FSTR + j*8 + tig*2) = make_float2(sacc[j][2], sacc[j][3]);
            }
            __syncwarp();

            #pragma unroll
            for (int kc = 0; kc < 8; kc++) {
                const int kb8 = kc * 8;
                uint32_t av[4];
                av[0] = F2U(ps[(m0+gid  )*FSTR + kb8+tig  ]);
                av[1] = F2U(ps[(m0+gid+8)*FSTR + kb8+tig  ]);
                av[2] = F2U(ps[(m0+gid  )*FSTR + kb8+tig+4]);
                av[3] = F2U(ps[(m0+gid+8)*FSTR + kb8+tig+4]);
                #pragma unroll
                for (int j = 0; j < 8; j++) {
                    uint32_t bv[2];
                    bv[0] = F2U(vs[(kb8+tig  )*VSTR + j*8+gid]);
                    bv[1] = F2U(vs[(kb8+tig+4)*VSTR + j*8+gid]);
                    mma_tf32(o[j], av, bv);
                }
            }
        }
        __syncthreads();         // vs consumed
        if (kt + 1 < ktmax) load_v(kt + 1);
        CP_COMMIT();             // V(kt+1) overlaps next S
    }

    const float inv0 = 1.0f / l_i[0];
    const float inv1 = 1.0f / l_i[1];
    float* ob = out + (size_t)b*PP*DD + (size_t)h*HDIM;
    #pragma unroll
    for (int j = 0; j < 8; j++) {
        int c = j*8 + tig*2;
        *(float2*)(ob + (size_t)(q0+m0+gid  )*DD + c) =
            make_float2(rna_tf32(o[j][0]*inv0), rna_tf32(o[j][1]*inv0));
        *(float2*)(ob + (size_t)(q0+m0+gid+8)*DD + c) =
            make_float2(rna_tf32(o[j][2]*inv1), rna_tf32(o[j][3]*inv1));
    }
}

// ---------------- launch ----------------
extern "C" void kernel_launch(void* const* d_in, const int* in_sizes, int n_in,
                              void* d_out, int out_size)
{
    const float* x        = (const float*)d_in[0];
    const float* emask    = (const float*)d_in[1];
    const float* ln1_w    = (const float*)d_in[2];
    const float* wq       = (const float*)d_in[3];
    const float* bq       = (const float*)d_in[4];
    const float* wk       = (const float*)d_in[5];
    const float* bk       = (const float*)d_in[6];
    const float* wv       = (const float*)d_in[7];
    const float* bv       = (const float*)d_in[8];
    const float* wo       = (const float*)d_in[9];
    const float* ln2_w    = (const float*)d_in[10];
    const float* w_gate   = (const float*)d_in[11];
    const float* w_up     = (const float*)d_in[12];
    const float* w_down   = (const float*)d_in[13];
    const float* we_gate  = (const float*)d_in[14];
    const float* we_up    = (const float*)d_in[15];
    const float* we_down  = (const float*)d_in[16];
    float* out = (float*)d_out;

    float *h,*q,*k,*v,*att,*x2,*h2,*gate,*up,*eg,*eu,*tmp;
    float *wqr,*wkr,*wvr,*wor,*wgr,*wur,*wdr,*wegr,*weur,*wedr,*ropet;
    cudaGetSymbolAddress((void**)&h,   g_h);
    cudaGetSymbolAddress((void**)&q,   g_q);
    cudaGetSymbolAddress((void**)&k,   g_k);
    cudaGetSymbolAddress((void**)&v,   g_v);
    cudaGetSymbolAddress((void**)&att, g_att);
    cudaGetSymbolAddress((void**)&x2,  g_x2);
    cudaGetSymbolAddress((void**)&h2,  g_h2);
    cudaGetSymbolAddress((void**)&gate,g_gate);
    cudaGetSymbolAddress((void**)&up,  g_up);
    cudaGetSymbolAddress((void**)&eg,  g_eg);
    cudaGetSymbolAddress((void**)&eu,  g_eu);
    cudaGetSymbolAddress((void**)&tmp, g_tmp);
    cudaGetSymbolAddress((void**)&wqr, g_wq);
    cudaGetSymbolAddress((void**)&wkr, g_wk);
    cudaGetSymbolAddress((void**)&wvr, g_wv);
    cudaGetSymbolAddress((void**)&wor, g_wo);
    cudaGetSymbolAddress((void**)&wgr, g_wg);
    cudaGetSymbolAddress((void**)&wur, g_wu);
    cudaGetSymbolAddress((void**)&wdr, g_wd);
    cudaGetSymbolAddress((void**)&wegr,g_weg);
    cudaGetSymbolAddress((void**)&weur,g_weu);
    cudaGetSymbolAddress((void**)&wedr,g_wed);
    cudaGetSymbolAddress((void**)&ropet,g_rope);

    cudaFuncSetAttribute(mgemm_kernel<0>, cudaFuncAttributeMaxDynamicSharedMemorySize, MG_SMEM);
    cudaFuncSetAttribute(mgemm_kernel<1>, cudaFuncAttributeMaxDynamicSharedMemorySize, MG_SMEM);
    cudaFuncSetAttribute(mgemm_kernel<2>, cudaFuncAttributeMaxDynamicSharedMemorySize, MG_SMEM);
    cudaFuncSetAttribute(mgemm_kernel<3>, cudaFuncAttributeMaxDynamicSharedMemorySize, MG_SMEM);
    cudaFuncSetAttribute(mgemm_kernel<4>, cudaFuncAttributeMaxDynamicSharedMemorySize, MG_SMEM);
    cudaFuncSetAttribute(flash_tc_kernel, cudaFuncAttributeMaxDynamicSharedMemorySize, FL_SMEM);

    // 0) pre-round weights to tf32-RNA; build rope table
    auto rw = [&](const float* src, float* dst, long n) {
        long n4 = n / 4;
        round_tf32_kernel<<<(unsigned)((n4 + 255) / 256), 256>>>(src, dst, n4);
    };
    rw(wq, wqr, (long)DD*DD);
    rw(wk, wkr, (long)DD*KVH*HDIM);
    rw(wv, wvr, (long)DD*KVH*HDIM);
    rw(wo, wor, (long)DD*DD);
    rw(w_gate, wgr, (long)DD*FFN);
    rw(w_up,   wur, (long)DD*FFN);
    rw(w_down, wdr, (long)FFN*DD);
    rw(we_gate, wegr, (long)NE*DD*FE);
    rw(we_up,   weur, (long)NE*DD*FE);
    rw(we_down, wedr, (long)NE*FE*DD);
    rope_table_kernel<<<PP*32/256, 256>>>(ropet);

    // 1) h = rmsnorm(x)
    rmsnorm_kernel<<<NTOK, 256>>>(x, ln1_w, h);

    // 2) QKV projections (+bias, rounded)
    mgemm_kernel<1><<<dim3(8,64,1), 256, MG_SMEM>>>(h, wqr, q, NTOK, 1024, 1024, 1024, bq, nullptr, nullptr, 0, 0);
    mgemm_kernel<1><<<dim3(4,64,1), 256, MG_SMEM>>>(h, wkr, k, NTOK,  512, 1024,  512, bk, nullptr, nullptr, 0, 0);
    mgemm_kernel<1><<<dim3(4,64,1), 256, MG_SMEM>>>(h, wvr, v, NTOK,  512, 1024,  512, bv, nullptr, nullptr, 0, 0);

    // 3) RoPE (table-based, rounded)
    {
        long tq = (long)NTOK * HH  * 32;
        rope_kernel<<<(unsigned)((tq + 255) / 256), 256>>>(q, ropet, HH, tq);
        long tk = (long)NTOK * KVH * 32;
        rope_kernel<<<(unsigned)((tk + 255) / 256), 256>>>(k, ropet, KVH, tk);
    }

    // 4) attention (tf32 tensor cores, v2)
    flash_tc_kernel<<<dim3(PP/QROWS, HH, BB), 256, FL_SMEM>>>(q, k, v, att);

    // 5) x2 = x + att @ wo
    mgemm_kernel<2><<<dim3(8,64,1), 256, MG_SMEM>>>(att, wor, x2, NTOK, 1024, 1024, 1024, nullptr, x, nullptr, 0, 0);

    // 6) h2 = rmsnorm(x2)
    rmsnorm_kernel<<<NTOK, 256>>>(x2, ln2_w, h2);

    // 7) dense MLP
    mgemm_kernel<0><<<dim3(32,64,1), 256, MG_SMEM>>>(h2, wur, up,   NTOK, 4096, 1024, 4096, nullptr, nullptr, nullptr, 0, 0);
    mgemm_kernel<3><<<dim3(32,64,1), 256, MG_SMEM>>>(h2, wgr, gate, NTOK, 4096, 1024, 4096, nullptr, up,      nullptr, 0, 0);
    mgemm_kernel<2><<<dim3(8,64,1),  256, MG_SMEM>>>(gate, wdr, tmp, NTOK, 1024, 4096, 1024, nullptr, x2,     nullptr, 0, 0);

    // 8) experts (z-batched)
    mgemm_kernel<0><<<dim3(2,64,NE), 256, MG_SMEM>>>(h2, weur, eu, NTOK, 256, 1024, 4096,
                                                     nullptr, nullptr, nullptr, (long)1024*256, 256);
    mgemm_kernel<4><<<dim3(2,64,NE), 256, MG_SMEM>>>(h2, wegr, eg, NTOK, 256, 1024, 4096,
                                                     nullptr, eu, emask, (long)1024*256, 256);
    // 9) out = tmp + expert_acts @ we_down
    mgemm_kernel<2><<<dim3(8,64,1), 256, MG_SMEM>>>(eg, wedr, out, NTOK, 1024, 4096, 1024, nullptr, tmp, nullptr, 0, 0);
}